// round 2
// baseline (speedup 1.0000x reference)
#include <cuda_runtime.h>
#include <cstdint>

#define Bdim 2
#define Tdim 1024
#define Edim 1024
#define Hdim 16
#define Ddim 64
#define Rdim 32
#define Mdim (Bdim*Tdim)

typedef unsigned long long ull;

__device__ float g_diff[(size_t)Mdim*Edim];
__device__ float g_z   [(size_t)Mdim*Edim];
__device__ float g_hdn [(size_t)Mdim*6*Rdim];
__device__ float g_dd  [(size_t)Mdim*6*Edim];
__device__ float g_proj[(size_t)Mdim*5*Edim];
__device__ float g_gate[(size_t)Mdim*Edim];
__device__ float g_wh  [(size_t)Mdim*Edim];
__device__ float g_wdec[(size_t)Mdim*Edim];
__device__ float g_vr  [(size_t)Mdim*Hdim];
__device__ float g_rwkv[(size_t)Mdim*Edim];
__device__ float g_a   [(size_t)Mdim*Edim];

__device__ __forceinline__ ull pack2(float lo, float hi){
    ull r; asm("mov.b64 %0, {%1, %2};" : "=l"(r) : "f"(lo), "f"(hi)); return r;
}
__device__ __forceinline__ void fma2(ull& d, ull a, ull b){
    asm("fma.rn.f32x2 %0, %1, %2, %3;" : "=l"(d) : "l"(a), "l"(b), "l"(d));
}
__device__ __forceinline__ float2 unpack2(ull v){
    float lo, hi; asm("mov.b64 {%0, %1}, %2;" : "=f"(lo), "=f"(hi) : "l"(v));
    return make_float2(lo, hi);
}

// K1: token shift -> diff, z
__global__ __launch_bounds__(256) void k_shift(const float* __restrict__ x,
                                               const float* __restrict__ mu_x){
    int idx = blockIdx.x*256 + threadIdx.x;
    int e = idx & (Edim-1);
    int m = idx >> 10;
    int t = m & (Tdim-1);
    float xv = x[idx];
    float lx = (t==0) ? 0.f : x[idx - Edim];
    float d  = lx - xv;
    float mt = xv + d*mu_x[e];
    g_diff[idx] = d;
    g_z[idx]    = xv + d*mt;
}

// K2: hdn = tanh(z @ Aw[g] + Ab[g])
__global__ __launch_bounds__(256) void k_loraA(const float* __restrict__ Aw,
                                               const float* __restrict__ Ab){
    __shared__ float zsm[64][36];
    __shared__ float wsm[32][32];
    int g  = blockIdx.y;
    int m0 = blockIdx.x*64;
    int tid = threadIdx.x;
    int n = tid & 31, ty = tid >> 5;
    float acc[8];
    #pragma unroll
    for (int i=0;i<8;i++) acc[i]=0.f;
    const float* wbase = Aw + (size_t)g*Edim*Rdim;
    for (int k0=0;k0<Edim;k0+=32){
        #pragma unroll
        for (int j=0;j<2;j++){
            int f = tid + j*256;
            int row = f>>3, c4 = (f&7)*4;
            *(float4*)&zsm[row][c4] = *(const float4*)&g_z[(size_t)(m0+row)*Edim + k0 + c4];
        }
        {
            int kk = tid>>3, c4 = (tid&7)*4;
            *(float4*)&wsm[kk][c4] = *(const float4*)&wbase[(size_t)(k0+kk)*Rdim + c4];
        }
        __syncthreads();
        #pragma unroll
        for (int kk=0;kk<32;kk++){
            float bw = wsm[kk][n];
            #pragma unroll
            for (int i=0;i<8;i++) acc[i] += zsm[ty*8+i][kk]*bw;
        }
        __syncthreads();
    }
    float bias = Ab[g*Rdim + n];
    #pragma unroll
    for (int i=0;i<8;i++)
        g_hdn[(size_t)(m0+ty*8+i)*192 + g*32 + n] = tanhf(acc[i] + bias);
}

// K3: dd = x + diff*(lam + hdn@Bw + Bb)
__global__ __launch_bounds__(256) void k_loraB(const float* __restrict__ x,
                                               const float* __restrict__ Bw,
                                               const float* __restrict__ lam,
                                               const float* __restrict__ Bb){
    __shared__ float hsm[16][32];
    int g  = blockIdx.z;
    int m0 = blockIdx.y*16;
    int tid = threadIdx.x;
    int e  = blockIdx.x*256 + tid;
    float wreg[32];
    const float* wb = Bw + (size_t)g*Rdim*Edim + e;
    #pragma unroll
    for (int r=0;r<32;r++) wreg[r] = wb[(size_t)r*Edim];
    {
        int f = tid;     hsm[f>>5][f&31] = g_hdn[(size_t)(m0+(f>>5))*192 + g*32 + (f&31)];
        f = tid + 256;   hsm[f>>5][f&31] = g_hdn[(size_t)(m0+(f>>5))*192 + g*32 + (f&31)];
    }
    __syncthreads();
    float base = lam[g*Edim + e] + Bb[g*Edim + e];
    #pragma unroll
    for (int mm=0;mm<16;mm++){
        float acc = base;
        #pragma unroll
        for (int r=0;r<32;r++) acc += hsm[mm][r]*wreg[r];
        int m = m0 + mm;
        size_t xi = (size_t)m*Edim + e;
        g_dd[((size_t)m*6 + g)*Edim + e] = x[xi] + g_diff[xi]*acc;
    }
}

// K4: per-head 64x64 GEMM. scheme0: unit=gb*16+h; scheme1: unit=h.
// mode 0 plain, 1 tanh, 2 exp(-exp(acc+bias))
__global__ __launch_bounds__(256) void k_headgemm(const float* __restrict__ in, int in_rstride,
                                                  const float* __restrict__ w,
                                                  const float* __restrict__ bias,
                                                  float* __restrict__ out, int out_rstride,
                                                  int scheme, int mode){
    __shared__ float ysm[64][68];
    __shared__ float wsm[64][64];
    int unit = blockIdx.y;
    int m0   = blockIdx.x*64;
    int colbase = (scheme==0) ? ((unit>>4)*Edim + (unit&15)*64) : (unit*64);
    const float* wb = w + (size_t)unit*4096;
    int tid = threadIdx.x;
    #pragma unroll
    for (int j=0;j<4;j++){
        int f = tid + j*256;
        int row = f>>4, c4 = (f&15)*4;
        *(float4*)&ysm[row][c4] = *(const float4*)&in[(size_t)(m0+row)*in_rstride + colbase + c4];
        *(float4*)&wsm[row][c4] = *(const float4*)&wb[row*64 + c4];
    }
    __syncthreads();
    int tx = tid&15, ty = tid>>4;
    int n0 = tx*4, m0r = ty*4;
    ull acc[4][2];
    #pragma unroll
    for (int i=0;i<4;i++){ acc[i][0]=0ull; acc[i][1]=0ull; }
    #pragma unroll 16
    for (int k=0;k<64;k++){
        ull b01 = *(const ull*)&wsm[k][n0];
        ull b23 = *(const ull*)&wsm[k][n0+2];
        #pragma unroll
        for (int i=0;i<4;i++){
            float a = ysm[m0r+i][k];
            ull a2 = pack2(a, a);
            fma2(acc[i][0], a2, b01);
            fma2(acc[i][1], a2, b23);
        }
    }
    #pragma unroll
    for (int i=0;i<4;i++){
        float2 lo = unpack2(acc[i][0]), hi = unpack2(acc[i][1]);
        float v[4] = {lo.x, lo.y, hi.x, hi.y};
        #pragma unroll
        for (int j=0;j<4;j++){
            float r = v[j];
            if (mode==1) r = tanhf(r);
            else if (mode==2) r = expf(-expf(r + bias[unit*64 + n0 + j]));
            v[j] = r;
        }
        *(float4*)&out[(size_t)(m0+m0r+i)*out_rstride + colbase + n0] =
            make_float4(v[0],v[1],v[2],v[3]);
    }
}

// K5: C[M,1024] = A @ W (+bias), 64x64 tile, f32x2
__global__ __launch_bounds__(256) void k_gemm(const float* __restrict__ A, int arstride,
                                              const float* __restrict__ W,
                                              const float* __restrict__ bias,
                                              float* __restrict__ C, int crstride){
    __shared__ float As2[64][36];
    __shared__ float Bs[16][64];
    int tid = threadIdx.x;
    int mBase = blockIdx.x*64, nBase = blockIdx.y*64;
    int tx = tid&15, ty = tid>>4;
    int n0 = tx*4, m0r = ty*4;
    int arow = tid>>2, akc4 = (tid&3)*4;
    int brow = tid>>4, bnc4 = (tid&15)*4;
    const float* aptr = A + (size_t)(mBase+arow)*arstride + akc4;
    const float* bptr = W + (size_t)brow*Edim + nBase + bnc4;
    ull acc[4][2];
    #pragma unroll
    for (int i=0;i<4;i++){ acc[i][0]=0ull; acc[i][1]=0ull; }
    float4 av = *(const float4*)(aptr);
    float4 bv = *(const float4*)(bptr);
    for (int k0=0;k0<Edim;k0+=16){
        *(float4*)&As2[arow][2*akc4]   = make_float4(av.x,av.x,av.y,av.y);
        *(float4*)&As2[arow][2*akc4+4] = make_float4(av.z,av.z,av.w,av.w);
        *(float4*)&Bs[brow][bnc4] = bv;
        __syncthreads();
        if (k0+16 < Edim){
            av = *(const float4*)(aptr + k0 + 16);
            bv = *(const float4*)(bptr + (size_t)(k0+16)*Edim);
        }
        #pragma unroll
        for (int k=0;k<16;k++){
            ull b01 = *(const ull*)&Bs[k][n0];
            ull b23 = *(const ull*)&Bs[k][n0+2];
            #pragma unroll
            for (int i=0;i<4;i++){
                ull a2 = *(const ull*)&As2[m0r+i][2*k];
                fma2(acc[i][0], a2, b01);
                fma2(acc[i][1], a2, b23);
            }
        }
        __syncthreads();
    }
    #pragma unroll
    for (int i=0;i<4;i++){
        float2 lo = unpack2(acc[i][0]), hi = unpack2(acc[i][1]);
        float4 o = make_float4(lo.x, lo.y, hi.x, hi.y);
        if (bias){
            o.x += bias[nBase+n0+0]; o.y += bias[nBase+n0+1];
            o.z += bias[nBase+n0+2]; o.w += bias[nBase+n0+3];
        }
        *(float4*)&C[(size_t)(mBase+m0r+i)*crstride + nBase + n0] = o;
    }
}

// K6: vr[m,h] = dot(v,r)
__global__ __launch_bounds__(256) void k_vr(){
    int unit = blockIdx.x*8 + (threadIdx.x>>5);
    int lane = threadIdx.x & 31;
    int m = unit>>4, h = unit&15;
    const float* v = g_proj + ((size_t)m*5+1)*Edim + h*64;
    const float* r = g_proj + ((size_t)m*5+2)*Edim + h*64;
    float s = v[lane]*r[lane] + v[lane+32]*r[lane+32];
    #pragma unroll
    for (int o=16;o;o>>=1) s += __shfl_xor_sync(0xffffffffu, s, o);
    if (lane==0) g_vr[unit] = s;
}

// K7: WKV recurrence. 32 blocks (b,h), 256 thr, 4 thr/state-row, 16 cols each.
__global__ __launch_bounds__(256) void k_recur(){
    int unit = blockIdx.x;
    int b = unit >> 4, h = unit & 15;
    int tid = threadIdx.x;
    int row = tid >> 2, q = tid & 3, c0 = q*16;
    __shared__ float sv[2][64], sr[2][64];
    float S[16];
    #pragma unroll
    for (int j=0;j<16;j++) S[j] = 0.f;
    float kk=0.f, ww=0.f, uu=0.f, vrs=0.f, stage=0.f;
    int mbase = b*Tdim;
    {
        const float* bp = g_proj + (size_t)mbase*5*Edim + h*64;
        kk = bp[row]; uu = bp[4*Edim + row];
        if (tid < 64) stage = bp[Edim + tid];
        else if (tid < 128) stage = bp[2*Edim + tid - 64];
        ww = g_wdec[(size_t)mbase*Edim + h*64 + row];
        vrs = g_vr[mbase*Hdim + h];
    }
    int p = 0;
    for (int t=0;t<Tdim;t++){
        if (tid < 64)       sv[p][tid]    = stage;
        else if (tid < 128) sr[p][tid-64] = stage;
        __syncthreads();
        float kc=kk, wc=ww, uc=uu, vc=vrs;
        if (t+1 < Tdim){
            int mm = mbase + t + 1;
            const float* bp = g_proj + (size_t)mm*5*Edim + h*64;
            kk = bp[row]; uu = bp[4*Edim + row];
            if (tid < 64) stage = bp[Edim + tid];
            else if (tid < 128) stage = bp[2*Edim + tid - 64];
            ww = g_wdec[(size_t)mm*Edim + h*64 + row];
            vrs = g_vr[mm*Hdim + h];
        }
        const float4* rv4 = (const float4*)(&sr[p][c0]);
        const float4* vv4 = (const float4*)(&sv[p][c0]);
        float d0=0.f,d1=0.f,d2=0.f,d3=0.f;
        #pragma unroll
        for (int jj=0;jj<4;jj++){
            float4 rr = rv4[jj];
            d0 += S[jj*4+0]*rr.x; d1 += S[jj*4+1]*rr.y;
            d2 += S[jj*4+2]*rr.z; d3 += S[jj*4+3]*rr.w;
        }
        float dot = (d0+d1)+(d2+d3);
        dot += __shfl_xor_sync(0xffffffffu, dot, 1);
        dot += __shfl_xor_sync(0xffffffffu, dot, 2);
        if (q==0)
            g_rwkv[(size_t)(mbase+t)*Edim + h*64 + row] = uc*kc*vc + dot;
        #pragma unroll
        for (int jj=0;jj<4;jj++){
            float4 vv = vv4[jj];
            S[jj*4+0] = kc*vv.x + wc*S[jj*4+0];
            S[jj*4+1] = kc*vv.y + wc*S[jj*4+1];
            S[jj*4+2] = kc*vv.z + wc*S[jj*4+2];
            S[jj*4+3] = kc*vv.w + wc*S[jj*4+3];
        }
        p ^= 1;
    }
}

// K8: GroupNorm(16 groups, eps=1e-3) * silu(gate)
__global__ __launch_bounds__(256) void k_gn(const float* __restrict__ gamma,
                                            const float* __restrict__ beta){
    int unit = blockIdx.x*8 + (threadIdx.x>>5);
    int lane = threadIdx.x & 31;
    int m = unit>>4, h = unit&15;
    size_t base = (size_t)m*Edim + h*64;
    float v1 = g_rwkv[base + lane];
    float v2 = g_rwkv[base + 32 + lane];
    float s = v1+v2, sq = v1*v1 + v2*v2;
    #pragma unroll
    for (int o=16;o;o>>=1){
        s  += __shfl_xor_sync(0xffffffffu, s, o);
        sq += __shfl_xor_sync(0xffffffffu, sq, o);
    }
    float mean = s*(1.f/64.f);
    float var  = sq*(1.f/64.f) - mean*mean;
    float rstd = rsqrtf(var + 1e-3f);
    #pragma unroll
    for (int half=0; half<2; half++){
        int e = h*64 + half*32 + lane;
        float v = half ? v2 : v1;
        float nv = (v-mean)*rstd*gamma[e] + beta[e];
        float gg = g_gate[(size_t)m*Edim + e];
        g_a[(size_t)m*Edim + e] = nv * (gg/(1.f+expf(-gg)));
    }
}

extern "C" void kernel_launch(void* const* d_in, const int* in_sizes, int n_in,
                              void* d_out, int out_size) {
    const float* x    = (const float*)d_in[0];
    const float* mu_x = (const float*)d_in[1];
    const float* lam  = (const float*)d_in[2];
    const float* Aw   = (const float*)d_in[3];
    const float* Ab   = (const float*)d_in[4];
    const float* Bw   = (const float*)d_in[5];
    const float* Bb   = (const float*)d_in[6];
    const float* mhd  = (const float*)d_in[7];
    const float* gw   = (const float*)d_in[8];
    const float* wlam = (const float*)d_in[9];
    const float* wA   = (const float*)d_in[10];
    const float* wB   = (const float*)d_in[11];
    const float* gng  = (const float*)d_in[12];
    const float* gnb  = (const float*)d_in[13];
    const float* ow   = (const float*)d_in[14];
    const float* ob   = (const float*)d_in[15];
    float* out = (float*)d_out;

    float *p_dd, *p_proj, *p_wh, *p_wdec, *p_gate, *p_a;
    cudaGetSymbolAddress((void**)&p_dd,   g_dd);
    cudaGetSymbolAddress((void**)&p_proj, g_proj);
    cudaGetSymbolAddress((void**)&p_wh,   g_wh);
    cudaGetSymbolAddress((void**)&p_wdec, g_wdec);
    cudaGetSymbolAddress((void**)&p_gate, g_gate);
    cudaGetSymbolAddress((void**)&p_a,    g_a);

    k_shift<<<(Mdim*Edim)/256, 256>>>(x, mu_x);
    k_loraA<<<dim3(Mdim/64, 6), 256>>>(Aw, Ab);
    k_loraB<<<dim3(Edim/256, Mdim/16, 6), 256>>>(x, Bw, lam, Bb);
    k_headgemm<<<dim3(Mdim/64, 80), 256>>>(p_dd, 6*Edim, mhd, nullptr, p_proj, 5*Edim, 0, 0);
    k_gemm<<<dim3(Mdim/64, Edim/64), 256>>>(p_dd + 5*Edim, 6*Edim, gw, nullptr, p_gate, Edim);
    k_headgemm<<<dim3(Mdim/64, 16), 256>>>(p_proj + 3*Edim, 5*Edim, wA, nullptr, p_wh, Edim, 1, 1);
    k_headgemm<<<dim3(Mdim/64, 16), 256>>>(p_wh, Edim, wB, wlam, p_wdec, Edim, 1, 2);
    k_vr<<<(Mdim*Hdim)/8, 256>>>();
    k_recur<<<Bdim*Hdim, 256>>>();
    k_gn<<<(Mdim*Hdim)/8, 256>>>(gng, gnb);
    k_gemm<<<dim3(Mdim/64, Edim/64), 256>>>(p_a, Edim, ow, ob, out, Edim);
}

// round 4
// speedup vs baseline: 1.6692x; 1.6692x over previous
#include <cuda_runtime.h>
#include <cstdint>

#define Bdim 2
#define Tdim 1024
#define Edim 1024
#define Hdim 16
#define Ddim 64
#define Rdim 32
#define Mdim (Bdim*Tdim)
#define CH 16

typedef unsigned long long ull;

__device__ float g_diff[(size_t)Mdim*Edim];
__device__ float g_z   [(size_t)Mdim*Edim];
__device__ float g_hdn [(size_t)Mdim*6*Rdim];
__device__ float g_dd  [(size_t)Mdim*6*Edim];
__device__ float g_proj[(size_t)Mdim*5*Edim];
__device__ float g_gate[(size_t)Mdim*Edim];
__device__ float g_wh  [(size_t)Mdim*Edim];
__device__ float g_wdec[(size_t)Mdim*Edim];
__device__ float g_vr  [(size_t)Mdim*Hdim];
__device__ float g_rwkv[(size_t)Mdim*Edim];
__device__ float g_a   [(size_t)Mdim*Edim];

__device__ __forceinline__ ull pack2(float lo, float hi){
    ull r; asm("mov.b64 %0, {%1, %2};" : "=l"(r) : "f"(lo), "f"(hi)); return r;
}
__device__ __forceinline__ void fma2(ull& d, ull a, ull b){
    asm("fma.rn.f32x2 %0, %1, %2, %3;" : "=l"(d) : "l"(a), "l"(b), "l"(d));
}
__device__ __forceinline__ float2 unpack2(ull v){
    float lo, hi; asm("mov.b64 {%0, %1}, %2;" : "=f"(lo), "=f"(hi) : "l"(v));
    return make_float2(lo, hi);
}

// K1: token shift -> diff, z
__global__ __launch_bounds__(256) void k_shift(const float* __restrict__ x,
                                               const float* __restrict__ mu_x){
    int idx = blockIdx.x*256 + threadIdx.x;
    int e = idx & (Edim-1);
    int m = idx >> 10;
    int t = m & (Tdim-1);
    float xv = x[idx];
    float lx = (t==0) ? 0.f : x[idx - Edim];
    float d  = lx - xv;
    float mt = xv + d*mu_x[e];
    g_diff[idx] = d;
    g_z[idx]    = xv + d*mt;
}

// K2: hdn = tanh(z @ Aw[g] + Ab[g])
__global__ __launch_bounds__(256) void k_loraA(const float* __restrict__ Aw,
                                               const float* __restrict__ Ab){
    __shared__ float zsm[64][36];
    __shared__ float wsm[32][32];
    int g  = blockIdx.y;
    int m0 = blockIdx.x*64;
    int tid = threadIdx.x;
    int n = tid & 31, ty = tid >> 5;
    float acc[8];
    #pragma unroll
    for (int i=0;i<8;i++) acc[i]=0.f;
    const float* wbase = Aw + (size_t)g*Edim*Rdim;
    for (int k0=0;k0<Edim;k0+=32){
        #pragma unroll
        for (int j=0;j<2;j++){
            int f = tid + j*256;
            int row = f>>3, c4 = (f&7)*4;
            *(float4*)&zsm[row][c4] = *(const float4*)&g_z[(size_t)(m0+row)*Edim + k0 + c4];
        }
        {
            int kk = tid>>3, c4 = (tid&7)*4;
            *(float4*)&wsm[kk][c4] = *(const float4*)&wbase[(size_t)(k0+kk)*Rdim + c4];
        }
        __syncthreads();
        #pragma unroll
        for (int kk=0;kk<32;kk++){
            float bw = wsm[kk][n];
            #pragma unroll
            for (int i=0;i<8;i++) acc[i] += zsm[ty*8+i][kk]*bw;
        }
        __syncthreads();
    }
    float bias = Ab[g*Rdim + n];
    #pragma unroll
    for (int i=0;i<8;i++)
        g_hdn[(size_t)(m0+ty*8+i)*192 + g*32 + n] = tanhf(acc[i] + bias);
}

// K3: dd = x + diff*(lam + hdn@Bw + Bb)
__global__ __launch_bounds__(256) void k_loraB(const float* __restrict__ x,
                                               const float* __restrict__ Bw,
                                               const float* __restrict__ lam,
                                               const float* __restrict__ Bb){
    __shared__ float hsm[16][32];
    int g  = blockIdx.z;
    int m0 = blockIdx.y*16;
    int tid = threadIdx.x;
    int e  = blockIdx.x*256 + tid;
    float wreg[32];
    const float* wb = Bw + (size_t)g*Rdim*Edim + e;
    #pragma unroll
    for (int r=0;r<32;r++) wreg[r] = wb[(size_t)r*Edim];
    {
        int f = tid;     hsm[f>>5][f&31] = g_hdn[(size_t)(m0+(f>>5))*192 + g*32 + (f&31)];
        f = tid + 256;   hsm[f>>5][f&31] = g_hdn[(size_t)(m0+(f>>5))*192 + g*32 + (f&31)];
    }
    __syncthreads();
    float base = lam[g*Edim + e] + Bb[g*Edim + e];
    #pragma unroll
    for (int mm=0;mm<16;mm++){
        float acc = base;
        #pragma unroll
        for (int r=0;r<32;r++) acc += hsm[mm][r]*wreg[r];
        int m = m0 + mm;
        size_t xi = (size_t)m*Edim + e;
        g_dd[((size_t)m*6 + g)*Edim + e] = x[xi] + g_diff[xi]*acc;
    }
}

// K4: per-head 64x64 GEMM, dup-A f32x2, dynamic smem.
// scheme0: unit=gb*16+h; scheme1: unit=h.  mode 0 plain, 1 tanh, 2 exp(-exp(acc+bias))
#define YROW 132
#define WROW 68
__global__ __launch_bounds__(256) void k_headgemm(const float* __restrict__ in, int in_rstride,
                                                  const float* __restrict__ w,
                                                  const float* __restrict__ bias,
                                                  float* __restrict__ out, int out_rstride,
                                                  int scheme, int mode){
    extern __shared__ float dynsm[];
    float* ysm2 = dynsm;                 // [64][YROW], dup: [row][2k],[2k+1]
    float* wsm  = dynsm + 64*YROW;       // [64][WROW]
    int unit = blockIdx.y;
    int m0   = blockIdx.x*64;
    int colbase = (scheme==0) ? ((unit>>4)*Edim + (unit&15)*64) : (unit*64);
    const float* wb = w + (size_t)unit*4096;
    int tid = threadIdx.x;
    #pragma unroll
    for (int j=0;j<4;j++){
        int f = tid + j*256;
        int row = f>>4, c4 = (f&15)*4;
        float4 a = *(const float4*)&in[(size_t)(m0+row)*in_rstride + colbase + c4];
        *(float4*)&ysm2[row*YROW + 2*c4]   = make_float4(a.x,a.x,a.y,a.y);
        *(float4*)&ysm2[row*YROW + 2*c4+4] = make_float4(a.z,a.z,a.w,a.w);
        *(float4*)&wsm[row*WROW + c4] = *(const float4*)&wb[row*64 + c4];
    }
    __syncthreads();
    int tx = tid&15, ty = tid>>4;
    int n0 = tx*4, m0r = ty*4;
    ull acc[4][2];
    #pragma unroll
    for (int i=0;i<4;i++){ acc[i][0]=0ull; acc[i][1]=0ull; }
    #pragma unroll 8
    for (int k2=0;k2<32;k2++){
        float4 b0 = *(const float4*)&wsm[(2*k2)*WROW + n0];
        float4 b1 = *(const float4*)&wsm[(2*k2+1)*WROW + n0];
        ull b0_01 = pack2(b0.x,b0.y), b0_23 = pack2(b0.z,b0.w);
        ull b1_01 = pack2(b1.x,b1.y), b1_23 = pack2(b1.z,b1.w);
        #pragma unroll
        for (int i=0;i<4;i++){
            float4 aa = *(const float4*)&ysm2[(m0r+i)*YROW + 4*k2];
            ull a0 = pack2(aa.x,aa.y), a1 = pack2(aa.z,aa.w);
            fma2(acc[i][0], a0, b0_01);
            fma2(acc[i][1], a0, b0_23);
            fma2(acc[i][0], a1, b1_01);
            fma2(acc[i][1], a1, b1_23);
        }
    }
    #pragma unroll
    for (int i=0;i<4;i++){
        float2 lo = unpack2(acc[i][0]), hi = unpack2(acc[i][1]);
        float v[4] = {lo.x, lo.y, hi.x, hi.y};
        #pragma unroll
        for (int j=0;j<4;j++){
            float r = v[j];
            if (mode==1) r = tanhf(r);
            else if (mode==2) r = expf(-expf(r + bias[unit*64 + n0 + j]));
            v[j] = r;
        }
        *(float4*)&out[(size_t)(m0+m0r+i)*out_rstride + colbase + n0] =
            make_float4(v[0],v[1],v[2],v[3]);
    }
}
#define HG_SMEM ((64*YROW + 64*WROW)*4)

// K5: C[M,1024] = A @ W (+bias). 128x64 tile, 256 thr, 8x4 per thread, dup-A f32x2.
__global__ __launch_bounds__(256) void k_gemm(const float* __restrict__ A, int arstride,
                                              const float* __restrict__ W,
                                              const float* __restrict__ bias,
                                              float* __restrict__ C, int crstride){
    __shared__ float As2[128][36];
    __shared__ float Bs[16][64];
    int tid = threadIdx.x;
    int mBase = blockIdx.x*128, nBase = blockIdx.y*64;
    int tx = tid&15, ty = tid>>4;
    int n0 = tx*4, m0r = ty*8;
    int arow = tid>>1, ks = (tid&1)*8;
    int brow = tid>>4, bnc4 = (tid&15)*4;
    const float* aptr = A + (size_t)(mBase+arow)*arstride + ks;
    const float* bptr = W + (size_t)brow*Edim + nBase + bnc4;
    ull acc[8][2];
    #pragma unroll
    for (int i=0;i<8;i++){ acc[i][0]=0ull; acc[i][1]=0ull; }
    float4 av1 = *(const float4*)(aptr);
    float4 av2 = *(const float4*)(aptr+4);
    float4 bv  = *(const float4*)(bptr);
    for (int k0=0;k0<Edim;k0+=16){
        *(float4*)&As2[arow][2*ks]    = make_float4(av1.x,av1.x,av1.y,av1.y);
        *(float4*)&As2[arow][2*ks+4]  = make_float4(av1.z,av1.z,av1.w,av1.w);
        *(float4*)&As2[arow][2*ks+8]  = make_float4(av2.x,av2.x,av2.y,av2.y);
        *(float4*)&As2[arow][2*ks+12] = make_float4(av2.z,av2.z,av2.w,av2.w);
        *(float4*)&Bs[brow][bnc4] = bv;
        __syncthreads();
        if (k0+16 < Edim){
            av1 = *(const float4*)(aptr + k0 + 16);
            av2 = *(const float4*)(aptr + k0 + 20);
            bv  = *(const float4*)(bptr + (size_t)(k0+16)*Edim);
        }
        #pragma unroll
        for (int k2=0;k2<8;k2++){
            float4 b0 = *(const float4*)&Bs[2*k2][n0];
            float4 b1 = *(const float4*)&Bs[2*k2+1][n0];
            ull b0_01 = pack2(b0.x,b0.y), b0_23 = pack2(b0.z,b0.w);
            ull b1_01 = pack2(b1.x,b1.y), b1_23 = pack2(b1.z,b1.w);
            #pragma unroll
            for (int i=0;i<8;i++){
                float4 aa = *(const float4*)&As2[m0r+i][4*k2];
                ull a0 = pack2(aa.x,aa.y), a1 = pack2(aa.z,aa.w);
                fma2(acc[i][0], a0, b0_01);
                fma2(acc[i][1], a0, b0_23);
                fma2(acc[i][0], a1, b1_01);
                fma2(acc[i][1], a1, b1_23);
            }
        }
        __syncthreads();
    }
    #pragma unroll
    for (int i=0;i<8;i++){
        float2 lo = unpack2(acc[i][0]), hi = unpack2(acc[i][1]);
        float4 o = make_float4(lo.x, lo.y, hi.x, hi.y);
        if (bias){
            o.x += bias[nBase+n0+0]; o.y += bias[nBase+n0+1];
            o.z += bias[nBase+n0+2]; o.w += bias[nBase+n0+3];
        }
        *(float4*)&C[(size_t)(mBase+m0r+i)*crstride + nBase + n0] = o;
    }
}

// K6: vr[m,h] = dot(v,r)
__global__ __launch_bounds__(256) void k_vr(){
    int unit = blockIdx.x*8 + (threadIdx.x>>5);
    int lane = threadIdx.x & 31;
    int m = unit>>4, h = unit&15;
    const float* v = g_proj + ((size_t)m*5+1)*Edim + h*64;
    const float* r = g_proj + ((size_t)m*5+2)*Edim + h*64;
    float s = v[lane]*r[lane] + v[lane+32]*r[lane+32];
    #pragma unroll
    for (int o=16;o;o>>=1) s += __shfl_xor_sync(0xffffffffu, s, o);
    if (lane==0) g_vr[unit] = s;
}

// K7: WKV recurrence, chunked CH=16. 32 blocks (b,h), 256 thr, 4 thr/row, 16 cols each.
__global__ __launch_bounds__(256) void k_recur(){
    int unit = blockIdx.x;
    int b = unit >> 4, h = unit & 15;
    int tid = threadIdx.x;
    int row = tid >> 2, q = tid & 3, c0 = q*16;
    __shared__ float sk[CH][64], su[CH][64], sw[CH][64], sv[CH][64], sr[CH][64];
    __shared__ float svr[CH], sout[CH][64];
    float S[16];
    #pragma unroll
    for (int j=0;j<16;j++) S[j] = 0.f;
    int mbase = b*Tdim;
    float rk[4], ru[4], rw[4], rv[4], rr[4], rvr = 0.f;

    #pragma unroll
    for (int it=0;it<4;it++){
        int idx = tid + it*256; int st = idx>>6, col = idx&63;
        size_t m = (size_t)(mbase + st);
        const float* bp = g_proj + m*5*Edim + h*64 + col;
        rk[it] = bp[0]; rv[it] = bp[Edim]; rr[it] = bp[2*Edim]; ru[it] = bp[4*Edim];
        rw[it] = g_wdec[m*Edim + h*64 + col];
    }
    if (tid < CH) rvr = g_vr[(mbase+tid)*Hdim + h];

    for (int c=0; c<Tdim/CH; c++){
        #pragma unroll
        for (int it=0;it<4;it++){
            int idx = tid + it*256; int st = idx>>6, col = idx&63;
            sk[st][col]=rk[it]; su[st][col]=ru[it]; sw[st][col]=rw[it];
            sv[st][col]=rv[it]; sr[st][col]=rr[it];
        }
        if (tid < CH) svr[tid] = rvr;
        __syncthreads();
        if (c+1 < Tdim/CH){
            int t0 = (c+1)*CH;
            #pragma unroll
            for (int it=0;it<4;it++){
                int idx = tid + it*256; int st = idx>>6, col = idx&63;
                size_t m = (size_t)(mbase + t0 + st);
                const float* bp = g_proj + m*5*Edim + h*64 + col;
                rk[it] = bp[0]; rv[it] = bp[Edim]; rr[it] = bp[2*Edim]; ru[it] = bp[4*Edim];
                rw[it] = g_wdec[m*Edim + h*64 + col];
            }
            if (tid < CH) rvr = g_vr[(mbase+t0+tid)*Hdim + h];
        }
        #pragma unroll
        for (int t=0;t<CH;t++){
            float kc = sk[t][row], wc = sw[t][row], uc = su[t][row], vc = svr[t];
            const float4* rv4 = (const float4*)&sr[t][c0];
            const float4* vv4 = (const float4*)&sv[t][c0];
            float d0=0.f,d1=0.f,d2=0.f,d3=0.f;
            #pragma unroll
            for (int jj=0;jj<4;jj++){
                float4 rrx = rv4[jj];
                d0 += S[jj*4+0]*rrx.x; d1 += S[jj*4+1]*rrx.y;
                d2 += S[jj*4+2]*rrx.z; d3 += S[jj*4+3]*rrx.w;
            }
            float dot = (d0+d1)+(d2+d3);
            dot += __shfl_xor_sync(0xffffffffu, dot, 1);
            dot += __shfl_xor_sync(0xffffffffu, dot, 2);
            if (q==0) sout[t][row] = uc*kc*vc + dot;
            #pragma unroll
            for (int jj=0;jj<4;jj++){
                float4 vv = vv4[jj];
                S[jj*4+0] = kc*vv.x + wc*S[jj*4+0];
                S[jj*4+1] = kc*vv.y + wc*S[jj*4+1];
                S[jj*4+2] = kc*vv.z + wc*S[jj*4+2];
                S[jj*4+3] = kc*vv.w + wc*S[jj*4+3];
            }
        }
        __syncthreads();
        #pragma unroll
        for (int it=0;it<4;it++){
            int idx = tid + it*256; int st = idx>>6, col = idx&63;
            g_rwkv[(size_t)(mbase + c*CH + st)*Edim + h*64 + col] = sout[st][col];
        }
    }
}

// K8: GroupNorm(16 groups, eps=1e-3) * silu(gate)
__global__ __launch_bounds__(256) void k_gn(const float* __restrict__ gamma,
                                            const float* __restrict__ beta){
    int unit = blockIdx.x*8 + (threadIdx.x>>5);
    int lane = threadIdx.x & 31;
    int m = unit>>4, h = unit&15;
    size_t base = (size_t)m*Edim + h*64;
    float v1 = g_rwkv[base + lane];
    float v2 = g_rwkv[base + 32 + lane];
    float s = v1+v2, sq = v1*v1 + v2*v2;
    #pragma unroll
    for (int o=16;o;o>>=1){
        s  += __shfl_xor_sync(0xffffffffu, s, o);
        sq += __shfl_xor_sync(0xffffffffu, sq, o);
    }
    float mean = s*(1.f/64.f);
    float var  = sq*(1.f/64.f) - mean*mean;
    float rstd = rsqrtf(var + 1e-3f);
    #pragma unroll
    for (int half=0; half<2; half++){
        int e = h*64 + half*32 + lane;
        float v = half ? v2 : v1;
        float nv = (v-mean)*rstd*gamma[e] + beta[e];
        float gg = g_gate[(size_t)m*Edim + e];
        g_a[(size_t)m*Edim + e] = nv * (gg/(1.f+expf(-gg)));
    }
}

extern "C" void kernel_launch(void* const* d_in, const int* in_sizes, int n_in,
                              void* d_out, int out_size) {
    const float* x    = (const float*)d_in[0];
    const float* mu_x = (const float*)d_in[1];
    const float* lam  = (const float*)d_in[2];
    const float* Aw   = (const float*)d_in[3];
    const float* Ab   = (const float*)d_in[4];
    const float* Bw   = (const float*)d_in[5];
    const float* Bb   = (const float*)d_in[6];
    const float* mhd  = (const float*)d_in[7];
    const float* gw   = (const float*)d_in[8];
    const float* wlam = (const float*)d_in[9];
    const float* wA   = (const float*)d_in[10];
    const float* wB   = (const float*)d_in[11];
    const float* gng  = (const float*)d_in[12];
    const float* gnb  = (const float*)d_in[13];
    const float* ow   = (const float*)d_in[14];
    const float* ob   = (const float*)d_in[15];
    float* out = (float*)d_out;

    float *p_dd, *p_proj, *p_wh, *p_wdec, *p_gate, *p_a;
    cudaGetSymbolAddress((void**)&p_dd,   g_dd);
    cudaGetSymbolAddress((void**)&p_proj, g_proj);
    cudaGetSymbolAddress((void**)&p_wh,   g_wh);
    cudaGetSymbolAddress((void**)&p_wdec, g_wdec);
    cudaGetSymbolAddress((void**)&p_gate, g_gate);
    cudaGetSymbolAddress((void**)&p_a,    g_a);

    static bool attr_done = false;
    if (!attr_done){
        cudaFuncSetAttribute(k_headgemm, cudaFuncAttributeMaxDynamicSharedMemorySize, HG_SMEM);
        attr_done = true;
    }

    k_shift<<<(Mdim*Edim)/256, 256>>>(x, mu_x);
    k_loraA<<<dim3(Mdim/64, 6), 256>>>(Aw, Ab);
    k_loraB<<<dim3(Edim/256, Mdim/16, 6), 256>>>(x, Bw, lam, Bb);
    k_headgemm<<<dim3(Mdim/64, 80), 256, HG_SMEM>>>(p_dd, 6*Edim, mhd, nullptr, p_proj, 5*Edim, 0, 0);
    k_gemm<<<dim3(Mdim/128, Edim/64), 256>>>(p_dd + 5*Edim, 6*Edim, gw, nullptr, p_gate, Edim);
    k_headgemm<<<dim3(Mdim/64, 16), 256, HG_SMEM>>>(p_proj + 3*Edim, 5*Edim, wA, nullptr, p_wh, Edim, 1, 1);
    k_headgemm<<<dim3(Mdim/64, 16), 256, HG_SMEM>>>(p_wh, Edim, wB, wlam, p_wdec, Edim, 1, 2);
    k_vr<<<(Mdim*Hdim)/8, 256>>>();
    k_recur<<<Bdim*Hdim, 256>>>();
    k_gn<<<(Mdim*Hdim)/8, 256>>>(gng, gnb);
    k_gemm<<<dim3(Mdim/128, Edim/64), 256>>>(p_a, Edim, ow, ob, out, Edim);
}